// round 3
// baseline (speedup 1.0000x reference)
#include <cuda_runtime.h>

#define BB 64
#define CC 32
#define KK 4096
#define NPIX (BB*CC*256)
#define MAXTOK 16384

__device__ float g_zrest[NPIX];
__device__ float g_zflat[MAXTOK*CC];
__device__ float g_zsq[MAXTOK];
__device__ float g_wsq[KK];
__device__ float g_pd[32768];
__device__ int   g_pi[32768];

typedef unsigned long long ull;

// ---------- fused init: zrest copy + wsq + level-0 downsample ----------
__global__ void k_init(const float* __restrict__ z, const float* __restrict__ w) {
    int bid = blockIdx.x;
    if (bid < 2048) {
        int i = bid * 256 + threadIdx.x;
        g_zrest[i] = z[i];
    } else if (bid < 2064) {
        int r = (bid - 2048) * 256 + threadIdx.x;
        const float* p = w + r * 32;
        float s = 0.f;
#pragma unroll
        for (int c = 0; c < 32; c++) s = __fadd_rn(s, __fmul_rn(p[c], p[c]));
        g_wsq[r] = s;
    } else {
        // level-0 prep: warp per token (pn=1, sub=16), read z directly
        int warp = threadIdx.x >> 5, lane = threadIdx.x & 31;
        int t = (bid - 2064) * 8 + warp;          // 0..63
        const float* base = z + (t * 32 + lane) * 256;
        float s = 0.f;
        for (int dy = 0; dy < 16; dy++)
            for (int dx = 0; dx < 16; dx++)
                s = __fadd_rn(s, base[dy * 16 + dx]);
        float zd = __fmul_rn(s, 1.f / 256.f);
        g_zflat[t * 32 + lane] = zd;
        float q = __fmul_rn(zd, zd);
#pragma unroll
        for (int off = 16; off; off >>= 1)
            q = __fadd_rn(q, __shfl_xor_sync(0xffffffffu, q, off));
        if (lane == 0) g_zsq[t] = q;
    }
}

// ---------- dist+argmin: 64 tok x 64 codes tile, packed f32x2 FMA ----------
// 128 threads: tx=tid&15 (code group of 4), ty=tid>>4 (token group of 8)
__global__ void __launch_bounds__(128) k_dist(const float* __restrict__ emb,
                                              int codesPerSplit, int iters) {
    __shared__ float zs[32][64];
    __shared__ float es[32][64];
    __shared__ float ws[64];
    int tid = threadIdx.x;
    int tx = tid & 15, ty = tid >> 4;
    int tb = blockIdx.x * 64;

    for (int s = tid; s < 256; s += 128) {
        int tok = s >> 2, part = s & 3;
        const float4* p = (const float4*)(g_zflat + (tb + tok) * 32 + part * 8);
        float4 a = p[0], b4 = p[1];
        int c0 = part * 8;
        zs[c0+0][tok]=a.x;  zs[c0+1][tok]=a.y;  zs[c0+2][tok]=a.z;  zs[c0+3][tok]=a.w;
        zs[c0+4][tok]=b4.x; zs[c0+5][tok]=b4.y; zs[c0+6][tok]=b4.z; zs[c0+7][tok]=b4.w;
    }
    float zq[8];
#pragma unroll
    for (int j = 0; j < 8; j++) zq[j] = g_zsq[tb + ty * 8 + j];

    float bd[8]; int bk[8];
#pragma unroll
    for (int j = 0; j < 8; j++) { bd[j] = __int_as_float(0x7f800000); bk[j] = 0; }

    int kbase = blockIdx.y * codesPerSplit;
    for (int it = 0; it < iters; it++) {
        int kb = kbase + it * 64;
        __syncthreads();
        for (int s = tid; s < 256; s += 128) {
            int code = s >> 2, part = s & 3;
            const float4* p = (const float4*)(emb + (kb + code) * 32 + part * 8);
            float4 a = p[0], b4 = p[1];
            int c0 = part * 8;
            es[c0+0][code]=a.x;  es[c0+1][code]=a.y;  es[c0+2][code]=a.z;  es[c0+3][code]=a.w;
            es[c0+4][code]=b4.x; es[c0+5][code]=b4.y; es[c0+6][code]=b4.z; es[c0+7][code]=b4.w;
        }
        if (tid < 64) ws[tid] = g_wsq[kb + tid];
        __syncthreads();

        ull acc[4][4];
#pragma unroll
        for (int p = 0; p < 4; p++)
#pragma unroll
            for (int k = 0; k < 4; k++) acc[p][k] = 0ull;

#pragma unroll 8
        for (int c = 0; c < 32; c++) {
            ulonglong2 za = *(const ulonglong2*)&zs[c][ty * 8];
            ulonglong2 zb = *(const ulonglong2*)&zs[c][ty * 8 + 4];
            ull zp[4] = {za.x, za.y, zb.x, zb.y};
            float4 e0 = *(const float4*)&es[c][tx * 4];
            ull ed[4];
            asm("mov.b64 %0, {%1, %1};" : "=l"(ed[0]) : "f"(e0.x));
            asm("mov.b64 %0, {%1, %1};" : "=l"(ed[1]) : "f"(e0.y));
            asm("mov.b64 %0, {%1, %1};" : "=l"(ed[2]) : "f"(e0.z));
            asm("mov.b64 %0, {%1, %1};" : "=l"(ed[3]) : "f"(e0.w));
#pragma unroll
            for (int p = 0; p < 4; p++)
#pragma unroll
                for (int k = 0; k < 4; k++)
                    asm("fma.rn.f32x2 %0, %1, %2, %0;"
                        : "+l"(acc[p][k]) : "l"(zp[p]), "l"(ed[k]));
        }

#pragma unroll
        for (int p = 0; p < 4; p++) {
#pragma unroll
            for (int k = 0; k < 4; k++) {
                float lo, hi;
                asm("mov.b64 {%0, %1}, %2;" : "=f"(lo), "=f"(hi) : "l"(acc[p][k]));
                int kk = kb + tx * 4 + k;
                float wv = ws[tx * 4 + k];
                float d0 = __fadd_rn(__fadd_rn(zq[2*p],   wv), __fmul_rn(-2.f, lo));
                float d1 = __fadd_rn(__fadd_rn(zq[2*p+1], wv), __fmul_rn(-2.f, hi));
                if (d0 < bd[2*p])   { bd[2*p]   = d0; bk[2*p]   = kk; }
                if (d1 < bd[2*p+1]) { bd[2*p+1] = d1; bk[2*p+1] = kk; }
            }
        }
    }

#pragma unroll
    for (int j = 0; j < 8; j++) {
        float d = bd[j]; int k = bk[j];
#pragma unroll
        for (int off = 8; off; off >>= 1) {
            float od = __shfl_xor_sync(0xffffffffu, d, off, 16);
            int   ok = __shfl_xor_sync(0xffffffffu, k, off, 16);
            if (od < d || (od == d && ok < k)) { d = od; k = ok; }
        }
        if (tx == 0) {
            int t = tb + ty * 8 + j;
            g_pd[t * gridDim.y + blockIdx.y] = d;
            g_pi[t * gridDim.y + blockIdx.y] = k;
        }
    }
}

// ---------- cubic (jax Keys a=-0.5) weights, renormalized ----------
template<int PN>
__device__ __forceinline__ void cubw(int o, float* w) {
    if (PN == 1) { w[0] = 1.f; return; }
    float s = __fadd_rn(__fmul_rn(__fadd_rn((float)o, 0.5f), (float)PN / 16.f), -0.5f);
    float tot = 0.f;
#pragma unroll
    for (int i = 0; i < PN; i++) {
        float x = fabsf(s - (float)i);
        float v;
        if (x >= 2.f)      v = 0.f;
        else if (x >= 1.f) v = ((-0.5f * x + 2.5f) * x - 4.f) * x + 2.f;
        else               v = ((1.5f * x - 2.5f) * x) * x + 1.f;
        w[i] = v; tot += v;
    }
#pragma unroll
    for (int i = 0; i < PN; i++) w[i] = w[i] / tot;
}

// ---------- fused: ksplit-reduce + gather + bicubic + zrest + next prep -----
// PN = this level's pn, PNN = next level's pn (levels 0..3)
template<int PN, int PNN>
__global__ void __launch_bounds__(256) k_up(const float* __restrict__ emb,
                                            const float* __restrict__ outPrev,
                                            float* __restrict__ outCur,
                                            int isFirst, int KS) {
    constexpr int NT = PN * PN;
    constexpr int SUB = 16 / PNN;
    __shared__ float pdp[512];
    __shared__ int   pip[512];
    __shared__ int   tok_s[NT];
    __shared__ float ew[NT][33];
    int b = blockIdx.x;
    int tid = threadIdx.x;

    // Phase A: reduce K-split partials
    int tot = NT * KS;
    for (int i = tid; i < tot; i += 256) {
        pdp[i] = g_pd[b * tot + i];
        pip[i] = g_pi[b * tot + i];
    }
    __syncthreads();
    if (tid < NT) {
        float bdv = pdp[tid * KS]; int bkv = pip[tid * KS];
        for (int s = 1; s < KS; s++) {
            float d = pdp[tid * KS + s]; int k = pip[tid * KS + s];
            if (d < bdv || (d == bdv && k < bkv)) { bdv = d; bkv = k; }
        }
        tok_s[tid] = bkv;
    }
    __syncthreads();

    // Phase B: stage gathered embeddings
    for (int idx = tid; idx < NT * 8; idx += 256) {
        int token = idx >> 3, seg = idx & 7;
        float4 v = *(const float4*)(emb + tok_s[token] * 32 + seg * 4);
        ew[token][seg*4+0] = v.x; ew[token][seg*4+1] = v.y;
        ew[token][seg*4+2] = v.z; ew[token][seg*4+3] = v.w;
    }
    __syncthreads();

    // Phase C: bicubic up + out + zrest update + next-level downsample
    int y = tid >> 4, x = tid & 15;
    float wy[PN], wx[PN];
    cubw<PN>(y, wy);
    cubw<PN>(x, wx);
    float* px = pdp;   // reuse
    float zqacc = 0.f;
#pragma unroll
    for (int c = 0; c < 32; c++) {
        float acc = 0.f;
#pragma unroll
        for (int j = 0; j < PN; j++) {
            float tmp = 0.f;
#pragma unroll
            for (int i = 0; i < PN; i++) tmp += wx[i] * ew[j * PN + i][c];
            acc += wy[j] * tmp;
        }
        int idx = (b * 32 + c) * 256 + y * 16 + x;
        float prev = isFirst ? 0.f : outPrev[idx];
        outCur[idx] = prev + acc;
        float nz = g_zrest[idx] - acc;
        g_zrest[idx] = nz;
        if (SUB == 1) {
            g_zflat[(b * 256 + tid) * 32 + c] = nz;
            zqacc = __fadd_rn(zqacc, __fmul_rn(nz, nz));
        } else {
            px[tid] = nz;
            __syncthreads();
            if (tid < PNN * PNN) {
                int ty2 = tid / PNN, tx2 = tid % PNN;
                float s = 0.f;
                for (int dy = 0; dy < SUB; dy++)
                    for (int dx = 0; dx < SUB; dx++)
                        s = __fadd_rn(s, px[(ty2 * SUB + dy) * 16 + tx2 * SUB + dx]);
                float zd = __fmul_rn(s, 1.f / (float)(SUB * SUB));
                g_zflat[(b * PNN * PNN + tid) * 32 + c] = zd;
                zqacc = __fadd_rn(zqacc, __fmul_rn(zd, zd));
            }
            __syncthreads();
        }
    }
    if (SUB == 1) {
        g_zsq[b * 256 + tid] = zqacc;
    } else if (tid < PNN * PNN) {
        g_zsq[b * PNN * PNN + tid] = zqacc;
    }
}

// ---------- last level: reduce + gather + accumulate ----------
__global__ void __launch_bounds__(256) k_up_last(const float* __restrict__ emb,
                                                 const float* __restrict__ outPrev,
                                                 float* __restrict__ outCur, int KS) {
    __shared__ float pdp[512];
    __shared__ int   pip[512];
    __shared__ int   tok_s[256];
    int b = blockIdx.x, tid = threadIdx.x;
    int tot = 256 * KS;
    for (int i = tid; i < tot; i += 256) {
        pdp[i] = g_pd[b * tot + i];
        pip[i] = g_pi[b * tot + i];
    }
    __syncthreads();
    {
        float bdv = pdp[tid * KS]; int bkv = pip[tid * KS];
        for (int s = 1; s < KS; s++) {
            float d = pdp[tid * KS + s]; int k = pip[tid * KS + s];
            if (d < bdv || (d == bdv && k < bkv)) { bdv = d; bkv = k; }
        }
        tok_s[tid] = bkv;
    }
    __syncthreads();
    const float* e = emb + tok_s[tid] * 32;
#pragma unroll
    for (int c = 0; c < 32; c++) {
        int idx = (b * 32 + c) * 256 + tid;
        outCur[idx] = outPrev[idx] + e[c];
    }
}

extern "C" void kernel_launch(void* const* d_in, const int* in_sizes, int n_in,
                              void* d_out, int out_size) {
    const float* z = (const float*)d_in[0];
    const float* w = (const float*)d_in[1];
    float* out = (float*)d_out;

    k_init<<<2072, 256>>>(z, w);

    const int KSs[5]   = {64, 32, 16, 4, 2};
    const int gridx[5] = {1, 4, 16, 64, 256};

    for (int l = 0; l < 5; l++) {
        int KS = KSs[l];
        int cps = KK / KS;
        int iters = cps / 64;
        dim3 g(gridx[l], KS);
        k_dist<<<g, 128>>>(w, cps, iters);

        float* cur = out + (size_t)l * NPIX;
        const float* prev = (l == 0) ? out : out + (size_t)(l - 1) * NPIX;
        if      (l == 0) k_up<1, 2 ><<<64, 256>>>(w, prev, cur, 1, KS);
        else if (l == 1) k_up<2, 4 ><<<64, 256>>>(w, prev, cur, 0, KS);
        else if (l == 2) k_up<4, 8 ><<<64, 256>>>(w, prev, cur, 0, KS);
        else if (l == 3) k_up<8, 16><<<64, 256>>>(w, prev, cur, 0, KS);
        else             k_up_last<<<64, 256>>>(w, prev, cur, KS);
    }
}

// round 4
// speedup vs baseline: 1.0317x; 1.0317x over previous
#include <cuda_runtime.h>

#define BB 64
#define CC 32
#define KK 4096
#define NPIX (BB*CC*256)
#define MAXTOK 16384

__device__ float g_zrest[NPIX];
__device__ float g_zflat[MAXTOK*CC];
__device__ float g_zsq[MAXTOK];
__device__ float g_wsq[KK];
__device__ float g_pd[65536];
__device__ int   g_pi[65536];

typedef unsigned long long ull;

// ---------- fused init: zrest copy + wsq + level-0 downsample ----------
__global__ void k_init(const float* __restrict__ z, const float* __restrict__ w) {
    int bid = blockIdx.x;
    if (bid < 2048) {
        int i = bid * 256 + threadIdx.x;
        g_zrest[i] = z[i];
    } else if (bid < 2064) {
        int r = (bid - 2048) * 256 + threadIdx.x;
        const float* p = w + r * 32;
        float s = 0.f;
#pragma unroll
        for (int c = 0; c < 32; c++) s = __fadd_rn(s, __fmul_rn(p[c], p[c]));
        g_wsq[r] = s;
    } else {
        int warp = threadIdx.x >> 5, lane = threadIdx.x & 31;
        int t = (bid - 2064) * 8 + warp;          // 0..63
        const float* base = z + (t * 32 + lane) * 256;
        float s = 0.f;
        for (int dy = 0; dy < 16; dy++)
            for (int dx = 0; dx < 16; dx++)
                s = __fadd_rn(s, base[dy * 16 + dx]);
        float zd = __fmul_rn(s, 1.f / 256.f);
        g_zflat[t * 32 + lane] = zd;
        float q = __fmul_rn(zd, zd);
#pragma unroll
        for (int off = 16; off; off >>= 1)
            q = __fadd_rn(q, __shfl_xor_sync(0xffffffffu, q, off));
        if (lane == 0) g_zsq[t] = q;
    }
}

// ---------- dist+argmin: 128 tok x 64 codes tile, 256 thr, f32x2 FMA --------
// tx = tid&15 -> 4 codes, ty = tid>>4 -> 8 tokens (4 native f32x2 pairs)
__global__ void __launch_bounds__(256) k_dist(const float* __restrict__ emb,
                                              int codesPerSplit, int iters,
                                              int tokClamp) {
    __shared__ float zs[32][128];
    __shared__ ull   es[32][64];
    __shared__ float ws[64];
    int tid = threadIdx.x;
    int tx = tid & 15, ty = tid >> 4;
    int tb = blockIdx.x * 128;

    // stage z tile (c-major): 128 tok x 4 parts = 512 slots
    for (int s = tid; s < 512; s += 256) {
        int tok = s >> 2, part = s & 3;
        int gt = tb + tok; if (gt > tokClamp) gt = tokClamp;
        const float4* p = (const float4*)(g_zflat + gt * 32 + part * 8);
        float4 a = p[0], b4 = p[1];
        int c0 = part * 8;
        zs[c0+0][tok]=a.x;  zs[c0+1][tok]=a.y;  zs[c0+2][tok]=a.z;  zs[c0+3][tok]=a.w;
        zs[c0+4][tok]=b4.x; zs[c0+5][tok]=b4.y; zs[c0+6][tok]=b4.z; zs[c0+7][tok]=b4.w;
    }
    float zq[8];
#pragma unroll
    for (int j = 0; j < 8; j++) {
        int gt = tb + ty * 8 + j; if (gt > tokClamp) gt = tokClamp;
        zq[j] = g_zsq[gt];
    }

    float bd[8]; int bk[8];
#pragma unroll
    for (int j = 0; j < 8; j++) { bd[j] = __int_as_float(0x7f800000); bk[j] = 0; }

    int kbase = blockIdx.y * codesPerSplit;
    for (int it = 0; it < iters; it++) {
        int kb = kbase + it * 64;
        __syncthreads();
        // stage e tile pre-duplicated into both f32x2 halves: 64 codes x 4 parts
        {
            int code = tid >> 2, part = tid & 3;
            const float4* p = (const float4*)(emb + (kb + code) * 32 + part * 8);
            float4 a = p[0], b4 = p[1];
            int c0 = part * 8;
            ull d0,d1,d2,d3,d4,d5,d6,d7;
            asm("mov.b64 %0, {%1, %1};" : "=l"(d0) : "f"(a.x));
            asm("mov.b64 %0, {%1, %1};" : "=l"(d1) : "f"(a.y));
            asm("mov.b64 %0, {%1, %1};" : "=l"(d2) : "f"(a.z));
            asm("mov.b64 %0, {%1, %1};" : "=l"(d3) : "f"(a.w));
            asm("mov.b64 %0, {%1, %1};" : "=l"(d4) : "f"(b4.x));
            asm("mov.b64 %0, {%1, %1};" : "=l"(d5) : "f"(b4.y));
            asm("mov.b64 %0, {%1, %1};" : "=l"(d6) : "f"(b4.z));
            asm("mov.b64 %0, {%1, %1};" : "=l"(d7) : "f"(b4.w));
            es[c0+0][code]=d0; es[c0+1][code]=d1; es[c0+2][code]=d2; es[c0+3][code]=d3;
            es[c0+4][code]=d4; es[c0+5][code]=d5; es[c0+6][code]=d6; es[c0+7][code]=d7;
        }
        if (tid < 64) ws[tid] = g_wsq[kb + tid];
        __syncthreads();

        ull acc[4][4];
#pragma unroll
        for (int p = 0; p < 4; p++)
#pragma unroll
            for (int k = 0; k < 4; k++) acc[p][k] = 0ull;

#pragma unroll 8
        for (int c = 0; c < 32; c++) {
            ulonglong2 za = *(const ulonglong2*)&zs[c][ty * 8];
            ulonglong2 zb = *(const ulonglong2*)&zs[c][ty * 8 + 4];
            ull zp[4] = {za.x, za.y, zb.x, zb.y};
            ulonglong2 e01 = *(const ulonglong2*)&es[c][tx * 4];
            ulonglong2 e23 = *(const ulonglong2*)&es[c][tx * 4 + 2];
            ull ed[4] = {e01.x, e01.y, e23.x, e23.y};
#pragma unroll
            for (int p = 0; p < 4; p++)
#pragma unroll
                for (int k = 0; k < 4; k++)
                    asm("fma.rn.f32x2 %0, %1, %2, %0;"
                        : "+l"(acc[p][k]) : "l"(zp[p]), "l"(ed[k]));
        }

#pragma unroll
        for (int p = 0; p < 4; p++) {
#pragma unroll
            for (int k = 0; k < 4; k++) {
                float lo, hi;
                asm("mov.b64 {%0, %1}, %2;" : "=f"(lo), "=f"(hi) : "l"(acc[p][k]));
                int kk = kb + tx * 4 + k;
                float wv = ws[tx * 4 + k];
                float d0 = __fadd_rn(__fadd_rn(zq[2*p],   wv), __fmul_rn(-2.f, lo));
                float d1 = __fadd_rn(__fadd_rn(zq[2*p+1], wv), __fmul_rn(-2.f, hi));
                if (d0 < bd[2*p])   { bd[2*p]   = d0; bk[2*p]   = kk; }
                if (d1 < bd[2*p+1]) { bd[2*p+1] = d1; bk[2*p+1] = kk; }
            }
        }
    }

#pragma unroll
    for (int j = 0; j < 8; j++) {
        float d = bd[j]; int k = bk[j];
#pragma unroll
        for (int off = 8; off; off >>= 1) {
            float od = __shfl_xor_sync(0xffffffffu, d, off, 16);
            int   ok = __shfl_xor_sync(0xffffffffu, k, off, 16);
            if (od < d || (od == d && ok < k)) { d = od; k = ok; }
        }
        if (tx == 0) {
            int t = tb + ty * 8 + j;
            if (t <= tokClamp) {
                g_pd[t * gridDim.y + blockIdx.y] = d;
                g_pi[t * gridDim.y + blockIdx.y] = k;
            }
        }
    }
}

// ---------- cubic (jax Keys a=-0.5) weights, renormalized ----------
template<int PN>
__device__ __forceinline__ void cubw(int o, float* w) {
    if (PN == 1) { w[0] = 1.f; return; }
    float s = __fadd_rn(__fmul_rn(__fadd_rn((float)o, 0.5f), (float)PN / 16.f), -0.5f);
    float tot = 0.f;
#pragma unroll
    for (int i = 0; i < PN; i++) {
        float x = fabsf(s - (float)i);
        float v;
        if (x >= 2.f)      v = 0.f;
        else if (x >= 1.f) v = ((-0.5f * x + 2.5f) * x - 4.f) * x + 2.f;
        else               v = ((1.5f * x - 2.5f) * x) * x + 1.f;
        w[i] = v; tot += v;
    }
#pragma unroll
    for (int i = 0; i < PN; i++) w[i] = w[i] / tot;
}

// ---------- fused: ksplit-reduce + gather + bicubic + zrest + next prep -----
template<int PN, int PNN>
__global__ void __launch_bounds__(256) k_up(const float* __restrict__ emb,
                                            const float* __restrict__ outPrev,
                                            float* __restrict__ outCur,
                                            int isFirst, int KS) {
    constexpr int NT = PN * PN;
    constexpr int SUB = 16 / PNN;
    __shared__ float pdp[512];
    __shared__ int   pip[512];
    __shared__ int   tok_s[NT];
    __shared__ float ew[NT][33];
    __shared__ float zt[32][256];
    int b = blockIdx.x;
    int tid = threadIdx.x;

    // Phase A: reduce K-split partials
    int tot = NT * KS;
    for (int i = tid; i < tot; i += 256) {
        pdp[i] = g_pd[b * tot + i];
        pip[i] = g_pi[b * tot + i];
    }
    __syncthreads();
    if (tid < NT) {
        float bdv = pdp[tid * KS]; int bkv = pip[tid * KS];
        for (int s = 1; s < KS; s++) {
            float d = pdp[tid * KS + s]; int k = pip[tid * KS + s];
            if (d < bdv || (d == bdv && k < bkv)) { bdv = d; bkv = k; }
        }
        tok_s[tid] = bkv;
    }
    __syncthreads();

    // Phase B: stage gathered embeddings
    for (int idx = tid; idx < NT * 8; idx += 256) {
        int token = idx >> 3, seg = idx & 7;
        float4 v = *(const float4*)(emb + tok_s[token] * 32 + seg * 4);
        ew[token][seg*4+0] = v.x; ew[token][seg*4+1] = v.y;
        ew[token][seg*4+2] = v.z; ew[token][seg*4+3] = v.w;
    }
    __syncthreads();

    // Phase C: bicubic up + out + zrest, buffering residual tile in smem
    int y = tid >> 4, x = tid & 15;
    float wy[PN], wx[PN];
    cubw<PN>(y, wy);
    cubw<PN>(x, wx);
#pragma unroll
    for (int c = 0; c < 32; c++) {
        float acc = 0.f;
#pragma unroll
        for (int j = 0; j < PN; j++) {
            float tmp = 0.f;
#pragma unroll
            for (int i = 0; i < PN; i++) tmp += wx[i] * ew[j * PN + i][c];
            acc += wy[j] * tmp;
        }
        int idx = (b * 32 + c) * 256 + y * 16 + x;
        float prev = isFirst ? 0.f : outPrev[idx];
        outCur[idx] = prev + acc;
        float nz = g_zrest[idx] - acc;
        g_zrest[idx] = nz;
        zt[c][tid] = nz;
    }
    __syncthreads();

    // Phase D: next-level downsample, one token per thread
    if (tid < PNN * PNN) {
        int ty2 = tid / PNN, tx2 = tid % PNN;
        float buf[32];
        float zqacc = 0.f;
#pragma unroll
        for (int c = 0; c < 32; c++) {
            float s = 0.f;
            for (int dy = 0; dy < SUB; dy++)
                for (int dx = 0; dx < SUB; dx++)
                    s = __fadd_rn(s, zt[c][(ty2 * SUB + dy) * 16 + tx2 * SUB + dx]);
            float zd = __fmul_rn(s, 1.f / (float)(SUB * SUB));
            buf[c] = zd;
            zqacc = __fadd_rn(zqacc, __fmul_rn(zd, zd));
        }
        float* dst = g_zflat + (b * PNN * PNN + tid) * 32;
#pragma unroll
        for (int s8 = 0; s8 < 8; s8++)
            *(float4*)(dst + s8 * 4) = make_float4(buf[s8*4], buf[s8*4+1],
                                                   buf[s8*4+2], buf[s8*4+3]);
        g_zsq[b * PNN * PNN + tid] = zqacc;
    }
}

// ---------- last level: reduce + gather + accumulate ----------
__global__ void __launch_bounds__(256) k_up_last(const float* __restrict__ emb,
                                                 const float* __restrict__ outPrev,
                                                 float* __restrict__ outCur, int KS) {
    __shared__ float pdp[1024];
    __shared__ int   pip[1024];
    __shared__ int   tok_s[256];
    int b = blockIdx.x, tid = threadIdx.x;
    int tot = 256 * KS;
    for (int i = tid; i < tot; i += 256) {
        pdp[i] = g_pd[b * tot + i];
        pip[i] = g_pi[b * tot + i];
    }
    __syncthreads();
    {
        float bdv = pdp[tid * KS]; int bkv = pip[tid * KS];
        for (int s = 1; s < KS; s++) {
            float d = pdp[tid * KS + s]; int k = pip[tid * KS + s];
            if (d < bdv || (d == bdv && k < bkv)) { bdv = d; bkv = k; }
        }
        tok_s[tid] = bkv;
    }
    __syncthreads();
    const float* e = emb + tok_s[tid] * 32;
#pragma unroll
    for (int c = 0; c < 32; c++) {
        int idx = (b * 32 + c) * 256 + tid;
        outCur[idx] = outPrev[idx] + e[c];
    }
}

extern "C" void kernel_launch(void* const* d_in, const int* in_sizes, int n_in,
                              void* d_out, int out_size) {
    const float* z = (const float*)d_in[0];
    const float* w = (const float*)d_in[1];
    float* out = (float*)d_out;

    k_init<<<2072, 256>>>(z, w);

    const int ntok[5]  = {64, 256, 1024, 4096, 16384};
    const int KSs[5]   = {64, 32, 16, 8, 4};

    for (int l = 0; l < 5; l++) {
        int KS = KSs[l];
        int cps = KK / KS;
        int iters = cps / 64;
        int gx = (ntok[l] + 127) / 128;
        dim3 g(gx, KS);
        k_dist<<<g, 256>>>(w, cps, iters, ntok[l] - 1);

        float* cur = out + (size_t)l * NPIX;
        const float* prev = (l == 0) ? out : out + (size_t)(l - 1) * NPIX;
        if      (l == 0) k_up<1, 2 ><<<64, 256>>>(w, prev, cur, 1, KS);
        else if (l == 1) k_up<2, 4 ><<<64, 256>>>(w, prev, cur, 0, KS);
        else if (l == 2) k_up<4, 8 ><<<64, 256>>>(w, prev, cur, 0, KS);
        else if (l == 3) k_up<8, 16><<<64, 256>>>(w, prev, cur, 0, KS);
        else             k_up_last<<<64, 256>>>(w, prev, cur, KS);
    }
}